// round 15
// baseline (speedup 1.0000x reference)
#include <cuda_runtime.h>
#include <cuda_fp16.h>
#include <cstdint>

#define NB   8
#define CC   256
#define HW   4096
#define MALL 320   // 32 Q rows + 32 K rows + 256 U rows

#define USCALE    4096.0f          // 2^12, lifts U''/z out of fp16 subnormal range
#define UNSCALE   (1.0f / 4096.0f)

// ---------------- device scratch ----------------
__device__ __align__(128) float g_WallT[CC * MALL];                 // [c][m]
__device__ __align__(128) float g_QKU[(size_t)NB * MALL * HW];      // [n][m][l] (only m<64 used)
__device__ __align__(128) float g_Z[(size_t)NB * HW];               // row sums z_i
__device__ __align__(128) int   g_Cnt[NB * 32];                     // per-(n, col-block) done counters
__device__ __align__(128) __half g_Uh[(size_t)NB * CC * HW];        // U·2^12 (pre-z, scaled in E' tail)
__device__ __align__(128) __half g_Ph[(size_t)NB * HW * HW];        // P^T [n][j][i] fp16

// ---------------- K0: combined weights; 4 output rows per block share one Wv sweep ----------------
__global__ void build_wall(const float* __restrict__ Wq, const float* __restrict__ Wk,
                           const float* __restrict__ Wv, const float* __restrict__ Wo,
                           const float* __restrict__ gammap) {
    int m0 = blockIdx.x * 4;   // grid 80
    int c  = threadIdx.x;      // 0..255
    // zero g_Z and counters
    for (int k = blockIdx.x * 256 + c; k < NB * HW; k += 80 * 256) g_Z[k] = 0.f;
    if (blockIdx.x == 0 && c < NB * 32) g_Cnt[c] = 0;

    if (m0 < 64) {
#pragma unroll
        for (int j = 0; j < 4; ++j) {
            int m = m0 + j;
            float v = (m < 32) ? Wq[m * CC + c] : Wk[(m - 32) * CC + c];
            g_WallT[c * MALL + m] = v;
        }
    } else {
        int o0 = m0 - 64;
        float acc[4] = {0.f, 0.f, 0.f, 0.f};
        for (int t = 0; t < CC; ++t) {
            float wv = Wv[t * CC + c];
#pragma unroll
            for (int j = 0; j < 4; ++j)
                acc[j] = fmaf(Wo[(o0 + j) * CC + t], wv, acc[j]);
        }
        float g = gammap[0];
#pragma unroll
        for (int j = 0; j < 4; ++j)
            g_WallT[c * MALL + m0 + j] = acc[j] * g;
    }
}

// ---------------- common PTX helpers ----------------
__device__ __forceinline__ unsigned packh2(float lo, float hi) {
    __half2 h = __floats2half2_rn(lo, hi);
    return *(unsigned*)&h;
}
__device__ __forceinline__ void mma16h(float c[4], const unsigned a[4], const unsigned b[2]) {
    asm volatile(
        "mma.sync.aligned.m16n8k16.row.col.f32.f16.f16.f32 "
        "{%0,%1,%2,%3}, {%4,%5,%6,%7}, {%8,%9}, {%0,%1,%2,%3};\n"
        : "+f"(c[0]), "+f"(c[1]), "+f"(c[2]), "+f"(c[3])
        : "r"(a[0]), "r"(a[1]), "r"(a[2]), "r"(a[3]), "r"(b[0]), "r"(b[1]));
}
__device__ __forceinline__ void cpa16(const void* s, const void* g) {
    unsigned sa = (unsigned)__cvta_generic_to_shared(s);
    asm volatile("cp.async.cg.shared.global [%0], [%1], 16;" :: "r"(sa), "l"(g));
}
__device__ __forceinline__ uint32_t smem_u32(const void* p) {
    return (uint32_t)__cvta_generic_to_shared(p);
}
__device__ __forceinline__ void ldm_x4(unsigned& r0, unsigned& r1, unsigned& r2, unsigned& r3,
                                       uint32_t addr) {
    asm volatile("ldmatrix.sync.aligned.m8n8.x4.shared.b16 {%0,%1,%2,%3}, [%4];"
                 : "=r"(r0), "=r"(r1), "=r"(r2), "=r"(r3) : "r"(addr));
}

// ---------------- K1: TN fp16-MMA GEMM. Block x=0 -> fp32 Q/K rows; x>0 -> fp16 U·2^12 ----------------
#define BM  64
#define BN  128
#define BKK 16
#define STG 3
#define APAD 76
#define BPAD 140

__global__ void __launch_bounds__(256) gemm_tn(
    const float* __restrict__ A, int lda,
    const float* __restrict__ B, long long Bbs, int ldb,
    float* __restrict__ Cqk, long long Cbs, int ldc,
    __half* __restrict__ Cu, long long Ubs,
    int K)
{
    __shared__ float As[STG][BKK][APAD];
    __shared__ float Bs[STG][BKK][BPAD];

    int n = blockIdx.z;
    B += (size_t)n * Bbs;

    int m_blk = blockIdx.x * BM, n_blk = blockIdx.y * BN;
    int tid = threadIdx.x, warp = tid >> 5, lane = tid & 31;
    int wm = (warp >> 2) * 32, wn = (warp & 3) * 32;
    int lr = lane >> 2, lc = lane & 3;

    float c[2][4][4];
#pragma unroll
    for (int i = 0; i < 2; ++i)
#pragma unroll
        for (int j = 0; j < 4; ++j)
#pragma unroll
            for (int q = 0; q < 4; ++q) c[i][j][q] = 0.f;

    int ar = tid >> 4, ac = (tid & 15) << 2;
    int KT = K / BKK;

    auto issue = [&](int kt, int buf) {
        cpa16(&As[buf][ar][ac], A + (size_t)(kt * BKK + ar) * lda + m_blk + ac);
#pragma unroll
        for (int i = 0; i < 2; ++i) {
            int idx = tid + (i << 8);
            int br = idx >> 5, bc = (idx & 31) << 2;
            cpa16(&Bs[buf][br][bc], B + (size_t)(kt * BKK + br) * ldb + n_blk + bc);
        }
    };

    for (int s = 0; s < STG - 1; ++s) {
        if (s < KT) issue(s, s);
        asm volatile("cp.async.commit_group;");
    }

    for (int kt = 0; kt < KT; ++kt) {
        asm volatile("cp.async.wait_group %0;" :: "n"(STG - 2));
        __syncthreads();
        int buf = kt % STG;

        unsigned a[2][4], b[4][2];
#pragma unroll
        for (int mt = 0; mt < 2; ++mt) {
            int mb = wm + mt * 16;
            a[mt][0] = packh2(As[buf][2*lc][mb+lr],     As[buf][2*lc+1][mb+lr]);
            a[mt][1] = packh2(As[buf][2*lc][mb+lr+8],   As[buf][2*lc+1][mb+lr+8]);
            a[mt][2] = packh2(As[buf][2*lc+8][mb+lr],   As[buf][2*lc+9][mb+lr]);
            a[mt][3] = packh2(As[buf][2*lc+8][mb+lr+8], As[buf][2*lc+9][mb+lr+8]);
        }
#pragma unroll
        for (int nt = 0; nt < 4; ++nt) {
            int nb = wn + nt * 8;
            b[nt][0] = packh2(Bs[buf][2*lc][nb+lr],   Bs[buf][2*lc+1][nb+lr]);
            b[nt][1] = packh2(Bs[buf][2*lc+8][nb+lr], Bs[buf][2*lc+9][nb+lr]);
        }
#pragma unroll
        for (int mt = 0; mt < 2; ++mt)
#pragma unroll
            for (int nt = 0; nt < 4; ++nt)
                mma16h(c[mt][nt], a[mt], b[nt]);

        __syncthreads();
        int nx = kt + STG - 1;
        if (nx < KT) issue(nx, nx % STG);
        asm volatile("cp.async.commit_group;");
    }

    if (blockIdx.x == 0) {
        float* C = Cqk + (size_t)n * Cbs;
#pragma unroll
        for (int mt = 0; mt < 2; ++mt)
#pragma unroll
            for (int nt = 0; nt < 4; ++nt) {
                int r0 = m_blk + wm + mt * 16 + lr;
                int c0 = n_blk + wn + nt * 8 + lc * 2;
                *(float2*)(C + (size_t)r0 * ldc + c0)       = make_float2(c[mt][nt][0], c[mt][nt][1]);
                *(float2*)(C + (size_t)(r0 + 8) * ldc + c0) = make_float2(c[mt][nt][2], c[mt][nt][3]);
            }
    } else {
        __half* U = Cu + (size_t)n * Ubs;
#pragma unroll
        for (int mt = 0; mt < 2; ++mt)
#pragma unroll
            for (int nt = 0; nt < 4; ++nt) {
                int r0 = m_blk - 64 + wm + mt * 16 + lr;
                int c0 = n_blk + wn + nt * 8 + lc * 2;
                *(__half2*)(U + (size_t)r0 * HW + c0) =
                    __floats2half2_rn(c[mt][nt][0] * USCALE, c[mt][nt][1] * USCALE);
                *(__half2*)(U + (size_t)(r0 + 8) * HW + c0) =
                    __floats2half2_rn(c[mt][nt][2] * USCALE, c[mt][nt][3] * USCALE);
            }
    }
}

// ---------------- E': P^T[j][i] = exp(e_ij); z_i col sums; LAST m-block scales U cols by 1/z ----------------
__global__ void __launch_bounds__(256) gemm_e(
    const float* __restrict__ A, long long Abs, int lda,
    const float* __restrict__ B, long long Bbs, int ldb,
    __half* __restrict__ C, long long Cbs, int ldc,
    float* __restrict__ gz, __half* __restrict__ Uall)
{
    __shared__ float As[STG][BKK][APAD];
    __shared__ float Bs[STG][BKK][BPAD];
    __shared__ float zpart[BN];
    __shared__ int lastFlag;

    int n = blockIdx.z;
    A += (size_t)n * Abs; B += (size_t)n * Bbs; C += (size_t)n * Cbs;

    int m_blk = blockIdx.y * BM, n_blk = blockIdx.x * BN;
    int tid = threadIdx.x, warp = tid >> 5, lane = tid & 31;
    int wm = (warp >> 2) * 32, wn = (warp & 3) * 32;
    int lr = lane >> 2, lc = lane & 3;

    float c[2][4][4];
#pragma unroll
    for (int i = 0; i < 2; ++i)
#pragma unroll
        for (int j = 0; j < 4; ++j)
#pragma unroll
            for (int q = 0; q < 4; ++q) c[i][j][q] = 0.f;

    if (tid < BN) zpart[tid] = 0.f;

    int ar = tid >> 4, ac = (tid & 15) << 2;
    const int KT = 32 / BKK;  // 2

    auto issue = [&](int kt, int buf) {
        cpa16(&As[buf][ar][ac], A + (size_t)(kt * BKK + ar) * lda + m_blk + ac);
#pragma unroll
        for (int i = 0; i < 2; ++i) {
            int idx = tid + (i << 8);
            int br = idx >> 5, bc = (idx & 31) << 2;
            cpa16(&Bs[buf][br][bc], B + (size_t)(kt * BKK + br) * ldb + n_blk + bc);
        }
    };

    for (int s = 0; s < STG - 1; ++s) {
        if (s < KT) issue(s, s);
        asm volatile("cp.async.commit_group;");
    }

    for (int kt = 0; kt < KT; ++kt) {
        asm volatile("cp.async.wait_group %0;" :: "n"(STG - 2));
        __syncthreads();
        int buf = kt % STG;

        unsigned a[2][4], b[4][2];
#pragma unroll
        for (int mt = 0; mt < 2; ++mt) {
            int mb = wm + mt * 16;
            a[mt][0] = packh2(As[buf][2*lc][mb+lr],     As[buf][2*lc+1][mb+lr]);
            a[mt][1] = packh2(As[buf][2*lc][mb+lr+8],   As[buf][2*lc+1][mb+lr+8]);
            a[mt][2] = packh2(As[buf][2*lc+8][mb+lr],   As[buf][2*lc+9][mb+lr]);
            a[mt][3] = packh2(As[buf][2*lc+8][mb+lr+8], As[buf][2*lc+9][mb+lr+8]);
        }
#pragma unroll
        for (int nt = 0; nt < 4; ++nt) {
            int nb = wn + nt * 8;
            b[nt][0] = packh2(Bs[buf][2*lc][nb+lr],   Bs[buf][2*lc+1][nb+lr]);
            b[nt][1] = packh2(Bs[buf][2*lc+8][nb+lr], Bs[buf][2*lc+9][nb+lr]);
        }
#pragma unroll
        for (int mt = 0; mt < 2; ++mt)
#pragma unroll
            for (int nt = 0; nt < 4; ++nt)
                mma16h(c[mt][nt], a[mt], b[nt]);

        __syncthreads();
        int nx = kt + STG - 1;
        if (nx < KT) issue(nx, nx % STG);
        asm volatile("cp.async.commit_group;");
    }

#pragma unroll
    for (int mt = 0; mt < 2; ++mt)
#pragma unroll
        for (int nt = 0; nt < 4; ++nt) {
#pragma unroll
            for (int q = 0; q < 4; ++q) c[mt][nt][q] = __expf(c[mt][nt][q]);
            int r0 = m_blk + wm + mt * 16 + lr;
            int c0 = n_blk + wn + nt * 8 + lc * 2;
            *(__half2*)(C + (size_t)r0 * ldc + c0) =
                __floats2half2_rn(c[mt][nt][0], c[mt][nt][1]);
            *(__half2*)(C + (size_t)(r0 + 8) * ldc + c0) =
                __floats2half2_rn(c[mt][nt][2], c[mt][nt][3]);
        }
#pragma unroll
    for (int nt = 0; nt < 4; ++nt) {
#pragma unroll
        for (int cp = 0; cp < 2; ++cp) {
            float v = c[0][nt][cp] + c[0][nt][cp + 2] + c[1][nt][cp] + c[1][nt][cp + 2];
            atomicAdd(&zpart[wn + nt * 8 + 2 * lc + cp], v);
        }
    }
    __syncthreads();
    if (tid < BN) atomicAdd(&gz[(size_t)n * HW + n_blk + tid], zpart[tid]);

    // ----- last-block tail: 64th finisher for this (n, col-block) scales U columns by 1/z -----
    __syncthreads();
    if (tid == 0) {
        __threadfence();   // order our gz writes before the counter bump
        int prev = atomicAdd(&g_Cnt[n * 32 + blockIdx.x], 1);
        lastFlag = (prev == (HW / BM) - 1);
    }
    __syncthreads();
    if (lastFlag) {
        // gz[n][n_blk .. n_blk+127] complete (all contributors fenced before bumping)
        __half* U = Uall + (size_t)n * CC * HW;
        const float* z = gz + (size_t)n * HW + n_blk;
        // 256 o-rows x 64 half2 per row
        for (int idx = tid; idx < CC * 64; idx += 256) {
            int o = idx >> 6, ip = idx & 63;
            __half2* u = (__half2*)(U + (size_t)o * HW + n_blk + 2 * ip);
            float2 v = __half22float2(*u);
            v.x /= z[2 * ip];
            v.y /= z[2 * ip + 1];
            *u = __floats2half2_rn(v.x, v.y);
        }
    }
}

// ================= K5 v7 (at HMMA issue floor): NT fp16 GEMM, 128x64 tiles, f32 accum =================
#define K5_BM   128
#define K5_BN   64
#define K5_BK   64
#define K5_STG  3
#define K5_A_BYTES 16384                     // 128 rows x 128 B
#define K5_B_BYTES 8192                      // 64 rows x 128 B
#define K5_STAGE   (K5_A_BYTES + K5_B_BYTES) // 24576
#define K5_SMEM    (K5_STG * K5_STAGE)       // 73728 bytes -> occ 3

#define SWZ(off) ((off) ^ (((off) >> 3) & 0x70))

__global__ void __launch_bounds__(256, 3) gemm_nt_f16_v7(
    const __half* __restrict__ A, const __half* __restrict__ B,
    float* __restrict__ C)
{
    extern __shared__ __align__(1024) char dsm[];
    uint32_t sbase = smem_u32(dsm);

    int n = blockIdx.z;
    const __half* Ab = A + (size_t)n * CC * HW + (size_t)(blockIdx.x * K5_BM) * HW;
    const __half* Bb = B + (size_t)n * HW * HW + (size_t)(blockIdx.y * K5_BN) * HW;
    float* Cb = C + (size_t)n * CC * HW + (size_t)(blockIdx.x * K5_BM) * HW + blockIdx.y * K5_BN;

    int tid = threadIdx.x, warp = tid >> 5, lane = tid & 31;
    int wm = (warp >> 1) * 32, wn = (warp & 1) * 32;   // 4x2 warp grid of 32x32 tiles
    int gr = lane >> 2, q4 = lane & 3;
    int sub = lane >> 3, rs = lane & 7;

    float c[2][4][4];
#pragma unroll
    for (int i = 0; i < 2; ++i)
#pragma unroll
        for (int j = 0; j < 4; ++j)
#pragma unroll
            for (int p = 0; p < 4; ++p) c[i][j][p] = 0.f;

    const int KT = HW / K5_BK;   // 64

    auto issue = [&](int kt, int s) {
        int k0 = kt * K5_BK;
        char* abase = dsm + (size_t)s * K5_STAGE;
        char* bbase = abase + K5_A_BYTES;
#pragma unroll
        for (int j = 0; j < 4; ++j) {
            int id = tid + (j << 8);
            int row = id >> 3, ch = id & 7;
            uint32_t so = SWZ((uint32_t)(row * 128 + ch * 16));
            cpa16(abase + so, Ab + (size_t)row * HW + k0 + ch * 8);
        }
#pragma unroll
        for (int j = 0; j < 2; ++j) {
            int id = tid + (j << 8);
            int row = id >> 3, ch = id & 7;
            uint32_t so = SWZ((uint32_t)(row * 128 + ch * 16));
            cpa16(bbase + so, Bb + (size_t)row * HW + k0 + ch * 8);
        }
    };

    issue(0, 0);
    asm volatile("cp.async.commit_group;");
    issue(1, 1);
    asm volatile("cp.async.commit_group;");

    int arow0 = wm + (sub & 1) * 8 + rs;
    int au    = sub >> 1;
    int brow0 = wn + (sub >> 1) * 8 + rs;
    int bu    = sub & 1;

    for (int kt = 0; kt < KT; ++kt) {
        asm volatile("cp.async.wait_group 1;");
        __syncthreads();
        int nx = kt + 2;
        if (nx < KT) issue(nx, nx % K5_STG);
        asm volatile("cp.async.commit_group;");

        int buf = kt % K5_STG;
        uint32_t aT = sbase + (uint32_t)buf * K5_STAGE;
        uint32_t bT = aT + K5_A_BYTES;

#pragma unroll
        for (int ks = 0; ks < 4; ++ks) {
            unsigned a[2][4], b[4][2];
#pragma unroll
            for (int mt = 0; mt < 2; ++mt) {
                uint32_t addr = aT + SWZ((uint32_t)((arow0 + mt * 16) * 128 + (ks * 2 + au) * 16));
                ldm_x4(a[mt][0], a[mt][1], a[mt][2], a[mt][3], addr);
            }
#pragma unroll
            for (int p = 0; p < 2; ++p) {
                uint32_t addr = bT + SWZ((uint32_t)((brow0 + p * 16) * 128 + (ks * 2 + bu) * 16));
                ldm_x4(b[2 * p][0], b[2 * p][1], b[2 * p + 1][0], b[2 * p + 1][1], addr);
            }
#pragma unroll
            for (int mt = 0; mt < 2; ++mt)
#pragma unroll
                for (int nt = 0; nt < 4; ++nt)
                    mma16h(c[mt][nt], a[mt], b[nt]);
        }
    }

#pragma unroll
    for (int mt = 0; mt < 2; ++mt) {
        int r0 = wm + mt * 16 + gr;
#pragma unroll
        for (int nt = 0; nt < 4; ++nt) {
            int c0 = wn + nt * 8 + 2 * q4;
            *(float2*)(Cb + (size_t)r0 * HW + c0) =
                make_float2(c[mt][nt][0] * UNSCALE, c[mt][nt][1] * UNSCALE);
            *(float2*)(Cb + (size_t)(r0 + 8) * HW + c0) =
                make_float2(c[mt][nt][2] * UNSCALE, c[mt][nt][3] * UNSCALE);
        }
    }
}

// ---------------- launch ----------------
extern "C" void kernel_launch(void* const* d_in, const int* in_sizes, int n_in,
                              void* d_out, int out_size) {
    const float* x  = (const float*)d_in[0];
    const float* Wq = (const float*)d_in[1];
    const float* Wk = (const float*)d_in[2];
    const float* Wv = (const float*)d_in[3];
    const float* Wo = (const float*)d_in[4];
    const float* gm = (const float*)d_in[5];
    float* out = (float*)d_out;

    float *wall, *qku, *gz;
    __half *uh, *ph;
    cudaGetSymbolAddress((void**)&wall, g_WallT);
    cudaGetSymbolAddress((void**)&qku,  g_QKU);
    cudaGetSymbolAddress((void**)&gz,   g_Z);
    cudaGetSymbolAddress((void**)&uh,   g_Uh);
    cudaGetSymbolAddress((void**)&ph,   g_Ph);

    // K0: combined weights (4 rows/block share Wv sweep) + zero z and counters
    build_wall<<<80, 256>>>(Wq, Wk, Wv, Wo, gm);

    // K1: Q/K rows -> fp32 g_QKU (block x=0); U rows -> fp16*2^12 g_Uh (blocks x>0)
    gemm_tn<<<dim3(MALL / BM, HW / BN, NB), 256>>>(
        wall, MALL,
        x, (long long)CC * HW, HW,
        qku, (long long)MALL * HW, HW,
        uh, (long long)CC * HW,
        CC);

    // E': P^T = exp(K^T x Q) fp16 + z col sums; last m-block per column scales U in place
    gemm_e<<<dim3(HW / BN, HW / BM, NB), 256>>>(
        qku + 32 * HW, (long long)MALL * HW, HW,    // A = K part
        qku,           (long long)MALL * HW, HW,    // B = Q part
        ph, (long long)HW * HW, HW,
        gz, uh);

    // K5 v7: fine-grained fp16 NT GEMM (128x64 tiles, f32 accum) — at HMMA issue floor
    cudaFuncSetAttribute(gemm_nt_f16_v7, cudaFuncAttributeMaxDynamicSharedMemorySize, K5_SMEM);
    gemm_nt_f16_v7<<<dim3(CC / K5_BM, HW / K5_BN, NB), 256, K5_SMEM>>>(uh, ph, out);
}

// round 16
// speedup vs baseline: 1.3600x; 1.3600x over previous
#include <cuda_runtime.h>
#include <cuda_fp16.h>
#include <cstdint>

#define NB   8
#define CC   256
#define HW   4096
#define MALL 320   // 32 Q rows + 32 K rows + 256 U rows

#define USCALE    4096.0f          // 2^12, lifts U''/z out of fp16 subnormal range
#define UNSCALE   (1.0f / 4096.0f)

// ---------------- device scratch ----------------
__device__ __align__(128) float g_WallT[CC * MALL];                 // [c][m]
__device__ __align__(128) float g_QKU[(size_t)NB * MALL * HW];      // [n][m][l] (only m<64 used)
__device__ __align__(128) float g_Z[(size_t)NB * HW];               // row sums z_i
__device__ __align__(128) __half g_Uh[(size_t)NB * CC * HW];        // U·2^12 (pre-z, scaled by zscale)
__device__ __align__(128) __half g_Ph[(size_t)NB * HW * HW];        // P^T [n][j][i] fp16

// ---------------- K0: combined weights; 4 output rows per block share one Wv sweep ----------------
__global__ void build_wall(const float* __restrict__ Wq, const float* __restrict__ Wk,
                           const float* __restrict__ Wv, const float* __restrict__ Wo,
                           const float* __restrict__ gammap) {
    int m0 = blockIdx.x * 4;   // grid 80
    int c  = threadIdx.x;      // 0..255
    for (int k = blockIdx.x * 256 + c; k < NB * HW; k += 80 * 256) g_Z[k] = 0.f;

    if (m0 < 64) {
#pragma unroll
        for (int j = 0; j < 4; ++j) {
            int m = m0 + j;
            float v = (m < 32) ? Wq[m * CC + c] : Wk[(m - 32) * CC + c];
            g_WallT[c * MALL + m] = v;
        }
    } else {
        int o0 = m0 - 64;
        float acc[4] = {0.f, 0.f, 0.f, 0.f};
        for (int t = 0; t < CC; ++t) {
            float wv = Wv[t * CC + c];
#pragma unroll
            for (int j = 0; j < 4; ++j)
                acc[j] = fmaf(Wo[(o0 + j) * CC + t], wv, acc[j]);
        }
        float g = gammap[0];
#pragma unroll
        for (int j = 0; j < 4; ++j)
            g_WallT[c * MALL + m0 + j] = acc[j] * g;
    }
}

// ---------------- common PTX helpers ----------------
__device__ __forceinline__ unsigned packh2(float lo, float hi) {
    __half2 h = __floats2half2_rn(lo, hi);
    return *(unsigned*)&h;
}
__device__ __forceinline__ void mma16h(float c[4], const unsigned a[4], const unsigned b[2]) {
    asm volatile(
        "mma.sync.aligned.m16n8k16.row.col.f32.f16.f16.f32 "
        "{%0,%1,%2,%3}, {%4,%5,%6,%7}, {%8,%9}, {%0,%1,%2,%3};\n"
        : "+f"(c[0]), "+f"(c[1]), "+f"(c[2]), "+f"(c[3])
        : "r"(a[0]), "r"(a[1]), "r"(a[2]), "r"(a[3]), "r"(b[0]), "r"(b[1]));
}
__device__ __forceinline__ void cpa16(const void* s, const void* g) {
    unsigned sa = (unsigned)__cvta_generic_to_shared(s);
    asm volatile("cp.async.cg.shared.global [%0], [%1], 16;" :: "r"(sa), "l"(g));
}
__device__ __forceinline__ uint32_t smem_u32(const void* p) {
    return (uint32_t)__cvta_generic_to_shared(p);
}
__device__ __forceinline__ void ldm_x4(unsigned& r0, unsigned& r1, unsigned& r2, unsigned& r3,
                                       uint32_t addr) {
    asm volatile("ldmatrix.sync.aligned.m8n8.x4.shared.b16 {%0,%1,%2,%3}, [%4];"
                 : "=r"(r0), "=r"(r1), "=r"(r2), "=r"(r3) : "r"(addr));
}

// ---------------- K1: TN fp16-MMA GEMM. Block x=0 -> fp32 Q/K rows; x>0 -> fp16 U·2^12 ----------------
#define BM  64
#define BN  128
#define BKK 16
#define STG 3
#define APAD 76
#define BPAD 140

__global__ void __launch_bounds__(256) gemm_tn(
    const float* __restrict__ A, int lda,
    const float* __restrict__ B, long long Bbs, int ldb,
    float* __restrict__ Cqk, long long Cbs, int ldc,
    __half* __restrict__ Cu, long long Ubs,
    int K)
{
    __shared__ float As[STG][BKK][APAD];
    __shared__ float Bs[STG][BKK][BPAD];

    int n = blockIdx.z;
    B += (size_t)n * Bbs;

    int m_blk = blockIdx.x * BM, n_blk = blockIdx.y * BN;
    int tid = threadIdx.x, warp = tid >> 5, lane = tid & 31;
    int wm = (warp >> 2) * 32, wn = (warp & 3) * 32;
    int lr = lane >> 2, lc = lane & 3;

    float c[2][4][4];
#pragma unroll
    for (int i = 0; i < 2; ++i)
#pragma unroll
        for (int j = 0; j < 4; ++j)
#pragma unroll
            for (int q = 0; q < 4; ++q) c[i][j][q] = 0.f;

    int ar = tid >> 4, ac = (tid & 15) << 2;
    int KT = K / BKK;

    auto issue = [&](int kt, int buf) {
        cpa16(&As[buf][ar][ac], A + (size_t)(kt * BKK + ar) * lda + m_blk + ac);
#pragma unroll
        for (int i = 0; i < 2; ++i) {
            int idx = tid + (i << 8);
            int br = idx >> 5, bc = (idx & 31) << 2;
            cpa16(&Bs[buf][br][bc], B + (size_t)(kt * BKK + br) * ldb + n_blk + bc);
        }
    };

    for (int s = 0; s < STG - 1; ++s) {
        if (s < KT) issue(s, s);
        asm volatile("cp.async.commit_group;");
    }

    for (int kt = 0; kt < KT; ++kt) {
        asm volatile("cp.async.wait_group %0;" :: "n"(STG - 2));
        __syncthreads();
        int buf = kt % STG;

        unsigned a[2][4], b[4][2];
#pragma unroll
        for (int mt = 0; mt < 2; ++mt) {
            int mb = wm + mt * 16;
            a[mt][0] = packh2(As[buf][2*lc][mb+lr],     As[buf][2*lc+1][mb+lr]);
            a[mt][1] = packh2(As[buf][2*lc][mb+lr+8],   As[buf][2*lc+1][mb+lr+8]);
            a[mt][2] = packh2(As[buf][2*lc+8][mb+lr],   As[buf][2*lc+9][mb+lr]);
            a[mt][3] = packh2(As[buf][2*lc+8][mb+lr+8], As[buf][2*lc+9][mb+lr+8]);
        }
#pragma unroll
        for (int nt = 0; nt < 4; ++nt) {
            int nb = wn + nt * 8;
            b[nt][0] = packh2(Bs[buf][2*lc][nb+lr],   Bs[buf][2*lc+1][nb+lr]);
            b[nt][1] = packh2(Bs[buf][2*lc+8][nb+lr], Bs[buf][2*lc+9][nb+lr]);
        }
#pragma unroll
        for (int mt = 0; mt < 2; ++mt)
#pragma unroll
            for (int nt = 0; nt < 4; ++nt)
                mma16h(c[mt][nt], a[mt], b[nt]);

        __syncthreads();
        int nx = kt + STG - 1;
        if (nx < KT) issue(nx, nx % STG);
        asm volatile("cp.async.commit_group;");
    }

    if (blockIdx.x == 0) {
        float* C = Cqk + (size_t)n * Cbs;
#pragma unroll
        for (int mt = 0; mt < 2; ++mt)
#pragma unroll
            for (int nt = 0; nt < 4; ++nt) {
                int r0 = m_blk + wm + mt * 16 + lr;
                int c0 = n_blk + wn + nt * 8 + lc * 2;
                *(float2*)(C + (size_t)r0 * ldc + c0)       = make_float2(c[mt][nt][0], c[mt][nt][1]);
                *(float2*)(C + (size_t)(r0 + 8) * ldc + c0) = make_float2(c[mt][nt][2], c[mt][nt][3]);
            }
    } else {
        __half* U = Cu + (size_t)n * Ubs;
#pragma unroll
        for (int mt = 0; mt < 2; ++mt)
#pragma unroll
            for (int nt = 0; nt < 4; ++nt) {
                int r0 = m_blk - 64 + wm + mt * 16 + lr;
                int c0 = n_blk + wn + nt * 8 + lc * 2;
                *(__half2*)(U + (size_t)r0 * HW + c0) =
                    __floats2half2_rn(c[mt][nt][0] * USCALE, c[mt][nt][1] * USCALE);
                *(__half2*)(U + (size_t)(r0 + 8) * HW + c0) =
                    __floats2half2_rn(c[mt][nt][2] * USCALE, c[mt][nt][3] * USCALE);
            }
    }
}

// ---------------- E' v2: 128x128 tiles, single-shot K=32, shuffle z-reduction ----------------
#define E_BM  128
#define E_BN  128
#define E_K   32
#define E_PAD 140

__global__ void __launch_bounds__(256) gemm_e2(
    const float* __restrict__ A, long long Abs, int lda,   // K rows [32][HW], m = j
    const float* __restrict__ B, long long Bbs, int ldb,   // Q rows [32][HW], n = i
    __half* __restrict__ C, long long Cbs, int ldc,
    float* __restrict__ gz)
{
    __shared__ float As[E_K][E_PAD];
    __shared__ float Bs[E_K][E_PAD];
    __shared__ float zpart[E_BN];

    int n = blockIdx.z;
    A += (size_t)n * Abs; B += (size_t)n * Bbs; C += (size_t)n * Cbs;

    int m_blk = blockIdx.y * E_BM, n_blk = blockIdx.x * E_BN;
    int tid = threadIdx.x, warp = tid >> 5, lane = tid & 31;
    int wm = (warp >> 1) * 32, wn = (warp & 1) * 64;
    int lr = lane >> 2, lc = lane & 3;

    if (tid < E_BN) zpart[tid] = 0.f;

    // single-shot load: 32 rows x 128 floats per matrix = 1024 16B chunks each; 8/thread
#pragma unroll
    for (int j = 0; j < 4; ++j) {
        int id = tid + (j << 8);        // 0..1023
        int row = id >> 3, col = (id & 7) << 4;   // col in floats: (id&7)*16... 
        // 128 floats/row = 32 chunks of 4 floats; id>>5 = row, (id&31)*4 = col
        row = id >> 5; col = (id & 31) << 2;
        cpa16(&As[row][col], A + (size_t)row * lda + m_blk + col);
        cpa16(&Bs[row][col], B + (size_t)row * ldb + n_blk + col);
    }
    asm volatile("cp.async.commit_group;");
    asm volatile("cp.async.wait_group 0;");
    __syncthreads();

    float c[2][8][4];
#pragma unroll
    for (int i = 0; i < 2; ++i)
#pragma unroll
        for (int j = 0; j < 8; ++j)
#pragma unroll
            for (int q = 0; q < 4; ++q) c[i][j][q] = 0.f;

#pragma unroll
    for (int ks = 0; ks < 2; ++ks) {
        int k0 = ks * 16;
        unsigned a[2][4], b[8][2];
#pragma unroll
        for (int mt = 0; mt < 2; ++mt) {
            int mb = wm + mt * 16;
            a[mt][0] = packh2(As[k0+2*lc][mb+lr],     As[k0+2*lc+1][mb+lr]);
            a[mt][1] = packh2(As[k0+2*lc][mb+lr+8],   As[k0+2*lc+1][mb+lr+8]);
            a[mt][2] = packh2(As[k0+2*lc+8][mb+lr],   As[k0+2*lc+9][mb+lr]);
            a[mt][3] = packh2(As[k0+2*lc+8][mb+lr+8], As[k0+2*lc+9][mb+lr+8]);
        }
#pragma unroll
        for (int nt = 0; nt < 8; ++nt) {
            int nb = wn + nt * 8;
            b[nt][0] = packh2(Bs[k0+2*lc][nb+lr],   Bs[k0+2*lc+1][nb+lr]);
            b[nt][1] = packh2(Bs[k0+2*lc+8][nb+lr], Bs[k0+2*lc+9][nb+lr]);
        }
#pragma unroll
        for (int mt = 0; mt < 2; ++mt)
#pragma unroll
            for (int nt = 0; nt < 8; ++nt)
                mma16h(c[mt][nt], a[mt], b[nt]);
    }

    // epilogue: exp, fp16 store, shuffle-reduced z column sums
#pragma unroll
    for (int mt = 0; mt < 2; ++mt)
#pragma unroll
        for (int nt = 0; nt < 8; ++nt) {
#pragma unroll
            for (int q = 0; q < 4; ++q) c[mt][nt][q] = __expf(c[mt][nt][q]);
            int r0 = m_blk + wm + mt * 16 + lr;
            int c0 = n_blk + wn + nt * 8 + lc * 2;
            *(__half2*)(C + (size_t)r0 * ldc + c0) =
                __floats2half2_rn(c[mt][nt][0], c[mt][nt][1]);
            *(__half2*)(C + (size_t)(r0 + 8) * ldc + c0) =
                __floats2half2_rn(c[mt][nt][2], c[mt][nt][3]);
        }
#pragma unroll
    for (int nt = 0; nt < 8; ++nt) {
#pragma unroll
        for (int cp = 0; cp < 2; ++cp) {
            float s = c[0][nt][cp] + c[0][nt][cp + 2] + c[1][nt][cp] + c[1][nt][cp + 2];
            s += __shfl_xor_sync(~0u, s, 4);
            s += __shfl_xor_sync(~0u, s, 8);
            s += __shfl_xor_sync(~0u, s, 16);
            if (lane < 4)
                atomicAdd(&zpart[wn + nt * 8 + 2 * lc + cp], s);
        }
    }
    __syncthreads();
    if (tid < E_BN) atomicAdd(&gz[(size_t)n * HW + n_blk + tid], zpart[tid]);
}

// ---------------- zscale: Uh[o][i] *= 1/z_i  (fp16 in place) ----------------
__global__ void zscale() {
    int n = blockIdx.y;
    int idx = blockIdx.x * blockDim.x + threadIdx.x;   // half2 index
    int base = idx * 2;
    int o = base >> 12;          // /4096
    int i = base & (HW - 1);
    __half2* u = (__half2*)(g_Uh + ((size_t)n * CC + o) * HW + i);
    const float* z = g_Z + (size_t)n * HW + i;
    float2 v = __half22float2(*u);
    v.x /= z[0];
    v.y /= z[1];
    *u = __floats2half2_rn(v.x, v.y);
}

// ================= K5 v7: NT fp16 GEMM, 128x64 tiles, f32 accum =================
#define K5_BM   128
#define K5_BN   64
#define K5_BK   64
#define K5_STG  3
#define K5_A_BYTES 16384                     // 128 rows x 128 B
#define K5_B_BYTES 8192                      // 64 rows x 128 B
#define K5_STAGE   (K5_A_BYTES + K5_B_BYTES) // 24576
#define K5_SMEM    (K5_STG * K5_STAGE)       // 73728 bytes -> occ 3

#define SWZ(off) ((off) ^ (((off) >> 3) & 0x70))

__global__ void __launch_bounds__(256, 3) gemm_nt_f16_v7(
    const __half* __restrict__ A, const __half* __restrict__ B,
    float* __restrict__ C)
{
    extern __shared__ __align__(1024) char dsm[];
    uint32_t sbase = smem_u32(dsm);

    int n = blockIdx.z;
    const __half* Ab = A + (size_t)n * CC * HW + (size_t)(blockIdx.x * K5_BM) * HW;
    const __half* Bb = B + (size_t)n * HW * HW + (size_t)(blockIdx.y * K5_BN) * HW;
    float* Cb = C + (size_t)n * CC * HW + (size_t)(blockIdx.x * K5_BM) * HW + blockIdx.y * K5_BN;

    int tid = threadIdx.x, warp = tid >> 5, lane = tid & 31;
    int wm = (warp >> 1) * 32, wn = (warp & 1) * 32;
    int gr = lane >> 2, q4 = lane & 3;
    int sub = lane >> 3, rs = lane & 7;

    float c[2][4][4];
#pragma unroll
    for (int i = 0; i < 2; ++i)
#pragma unroll
        for (int j = 0; j < 4; ++j)
#pragma unroll
            for (int p = 0; p < 4; ++p) c[i][j][p] = 0.f;

    const int KT = HW / K5_BK;   // 64

    auto issue = [&](int kt, int s) {
        int k0 = kt * K5_BK;
        char* abase = dsm + (size_t)s * K5_STAGE;
        char* bbase = abase + K5_A_BYTES;
#pragma unroll
        for (int j = 0; j < 4; ++j) {
            int id = tid + (j << 8);
            int row = id >> 3, ch = id & 7;
            uint32_t so = SWZ((uint32_t)(row * 128 + ch * 16));
            cpa16(abase + so, Ab + (size_t)row * HW + k0 + ch * 8);
        }
#pragma unroll
        for (int j = 0; j < 2; ++j) {
            int id = tid + (j << 8);
            int row = id >> 3, ch = id & 7;
            uint32_t so = SWZ((uint32_t)(row * 128 + ch * 16));
            cpa16(bbase + so, Bb + (size_t)row * HW + k0 + ch * 8);
        }
    };

    issue(0, 0);
    asm volatile("cp.async.commit_group;");
    issue(1, 1);
    asm volatile("cp.async.commit_group;");

    int arow0 = wm + (sub & 1) * 8 + rs;
    int au    = sub >> 1;
    int brow0 = wn + (sub >> 1) * 8 + rs;
    int bu    = sub & 1;

    for (int kt = 0; kt < KT; ++kt) {
        asm volatile("cp.async.wait_group 1;");
        __syncthreads();
        int nx = kt + 2;
        if (nx < KT) issue(nx, nx % K5_STG);
        asm volatile("cp.async.commit_group;");

        int buf = kt % K5_STG;
        uint32_t aT = sbase + (uint32_t)buf * K5_STAGE;
        uint32_t bT = aT + K5_A_BYTES;

#pragma unroll
        for (int ks = 0; ks < 4; ++ks) {
            unsigned a[2][4], b[4][2];
#pragma unroll
            for (int mt = 0; mt < 2; ++mt) {
                uint32_t addr = aT + SWZ((uint32_t)((arow0 + mt * 16) * 128 + (ks * 2 + au) * 16));
                ldm_x4(a[mt][0], a[mt][1], a[mt][2], a[mt][3], addr);
            }
#pragma unroll
            for (int p = 0; p < 2; ++p) {
                uint32_t addr = bT + SWZ((uint32_t)((brow0 + p * 16) * 128 + (ks * 2 + bu) * 16));
                ldm_x4(b[2 * p][0], b[2 * p][1], b[2 * p + 1][0], b[2 * p + 1][1], addr);
            }
#pragma unroll
            for (int mt = 0; mt < 2; ++mt)
#pragma unroll
                for (int nt = 0; nt < 4; ++nt)
                    mma16h(c[mt][nt], a[mt], b[nt]);
        }
    }

#pragma unroll
    for (int mt = 0; mt < 2; ++mt) {
        int r0 = wm + mt * 16 + gr;
#pragma unroll
        for (int nt = 0; nt < 4; ++nt) {
            int c0 = wn + nt * 8 + 2 * q4;
            *(float2*)(Cb + (size_t)r0 * HW + c0) =
                make_float2(c[mt][nt][0] * UNSCALE, c[mt][nt][1] * UNSCALE);
            *(float2*)(Cb + (size_t)(r0 + 8) * HW + c0) =
                make_float2(c[mt][nt][2] * UNSCALE, c[mt][nt][3] * UNSCALE);
        }
    }
}

// ---------------- launch ----------------
extern "C" void kernel_launch(void* const* d_in, const int* in_sizes, int n_in,
                              void* d_out, int out_size) {
    const float* x  = (const float*)d_in[0];
    const float* Wq = (const float*)d_in[1];
    const float* Wk = (const float*)d_in[2];
    const float* Wv = (const float*)d_in[3];
    const float* Wo = (const float*)d_in[4];
    const float* gm = (const float*)d_in[5];
    float* out = (float*)d_out;

    float *wall, *qku, *gz;
    __half *uh, *ph;
    cudaGetSymbolAddress((void**)&wall, g_WallT);
    cudaGetSymbolAddress((void**)&qku,  g_QKU);
    cudaGetSymbolAddress((void**)&gz,   g_Z);
    cudaGetSymbolAddress((void**)&uh,   g_Uh);
    cudaGetSymbolAddress((void**)&ph,   g_Ph);

    // K0: combined weights + zero z
    build_wall<<<80, 256>>>(Wq, Wk, Wv, Wo, gm);

    // K1: Q/K rows -> fp32 g_QKU (block x=0); U rows -> fp16*2^12 g_Uh (blocks x>0)
    gemm_tn<<<dim3(MALL / BM, HW / BN, NB), 256>>>(
        wall, MALL,
        x, (long long)CC * HW, HW,
        qku, (long long)MALL * HW, HW,
        uh, (long long)CC * HW,
        CC);

    // E' v2: 128x128 single-shot tiles, shuffle z-reduction
    gemm_e2<<<dim3(HW / E_BN, HW / E_BM, NB), 256>>>(
        qku + 32 * HW, (long long)MALL * HW, HW,    // A = K part
        qku,           (long long)MALL * HW, HW,    // B = Q part
        ph, (long long)HW * HW, HW,
        gz);

    // zscale: Uh *= 1/z  (fp16 in place)
    zscale<<<dim3(CC * HW / 512, NB), 256>>>();

    // K5 v7: fp16 NT GEMM (128x64 tiles, f32 accum)
    cudaFuncSetAttribute(gemm_nt_f16_v7, cudaFuncAttributeMaxDynamicSharedMemorySize, K5_SMEM);
    gemm_nt_f16_v7<<<dim3(CC / K5_BM, HW / K5_BN, NB), 256, K5_SMEM>>>(uh, ph, out);
}

// round 17
// speedup vs baseline: 1.4453x; 1.0627x over previous
#include <cuda_runtime.h>
#include <cuda_fp16.h>
#include <cstdint>

#define NB   8
#define CC   256
#define HW   4096
#define MALL 320   // 32 Q rows + 32 K rows + 256 U rows

#define USCALE    4096.0f
#define UNSCALE   (1.0f / 4096.0f)

// ---------------- device scratch ----------------
__device__ __align__(128) float g_WallT[CC * MALL];                 // [c][m]
__device__ __align__(128) float g_QKU[(size_t)NB * MALL * HW];      // [n][m][l] (only m<64 used)
__device__ __align__(128) float g_Z[(size_t)NB * HW];               // row sums z_i
__device__ __align__(128) __half g_Qh[(size_t)NB * HW * 32];        // Q^T fp16 [n][l][c']
__device__ __align__(128) __half g_Kh[(size_t)NB * HW * 32];        // K^T fp16 [n][l][c']
__device__ __align__(128) __half g_Uh[(size_t)NB * CC * HW];        // U·2^12 (pre-z)
__device__ __align__(128) __half g_Ph[(size_t)NB * HW * HW];        // P^T [n][j][i] fp16

// ---------------- K0: combined weights; 4 output rows per block share one Wv sweep ----------------
__global__ void build_wall(const float* __restrict__ Wq, const float* __restrict__ Wk,
                           const float* __restrict__ Wv, const float* __restrict__ Wo,
                           const float* __restrict__ gammap) {
    int m0 = blockIdx.x * 4;   // grid 80
    int c  = threadIdx.x;      // 0..255
    for (int k = blockIdx.x * 256 + c; k < NB * HW; k += 80 * 256) g_Z[k] = 0.f;

    if (m0 < 64) {
#pragma unroll
        for (int j = 0; j < 4; ++j) {
            int m = m0 + j;
            float v = (m < 32) ? Wq[m * CC + c] : Wk[(m - 32) * CC + c];
            g_WallT[c * MALL + m] = v;
        }
    } else {
        int o0 = m0 - 64;
        float acc[4] = {0.f, 0.f, 0.f, 0.f};
        for (int t = 0; t < CC; ++t) {
            float wv = Wv[t * CC + c];
#pragma unroll
            for (int j = 0; j < 4; ++j)
                acc[j] = fmaf(Wo[(o0 + j) * CC + t], wv, acc[j]);
        }
        float g = gammap[0];
#pragma unroll
        for (int j = 0; j < 4; ++j)
            g_WallT[c * MALL + m0 + j] = acc[j] * g;
    }
}

// ---------------- common PTX helpers ----------------
__device__ __forceinline__ unsigned packh2(float lo, float hi) {
    __half2 h = __floats2half2_rn(lo, hi);
    return *(unsigned*)&h;
}
__device__ __forceinline__ void mma16h(float c[4], const unsigned a[4], const unsigned b[2]) {
    asm volatile(
        "mma.sync.aligned.m16n8k16.row.col.f32.f16.f16.f32 "
        "{%0,%1,%2,%3}, {%4,%5,%6,%7}, {%8,%9}, {%0,%1,%2,%3};\n"
        : "+f"(c[0]), "+f"(c[1]), "+f"(c[2]), "+f"(c[3])
        : "r"(a[0]), "r"(a[1]), "r"(a[2]), "r"(a[3]), "r"(b[0]), "r"(b[1]));
}
__device__ __forceinline__ void cpa16(const void* s, const void* g) {
    unsigned sa = (unsigned)__cvta_generic_to_shared(s);
    asm volatile("cp.async.cg.shared.global [%0], [%1], 16;" :: "r"(sa), "l"(g));
}
__device__ __forceinline__ uint32_t smem_u32(const void* p) {
    return (uint32_t)__cvta_generic_to_shared(p);
}
__device__ __forceinline__ void ldm_x4(unsigned& r0, unsigned& r1, unsigned& r2, unsigned& r3,
                                       uint32_t addr) {
    asm volatile("ldmatrix.sync.aligned.m8n8.x4.shared.b16 {%0,%1,%2,%3}, [%4];"
                 : "=r"(r0), "=r"(r1), "=r"(r2), "=r"(r3) : "r"(addr));
}

// ---------------- K1: TN fp16-MMA GEMM. Block x=0 -> fp32 Q/K rows; x>0 -> fp16 U·2^12 ----------------
#define BM  64
#define BN  128
#define BKK 16
#define STG 3
#define APAD 76
#define BPAD 140

__global__ void __launch_bounds__(256) gemm_tn(
    const float* __restrict__ A, int lda,
    const float* __restrict__ B, long long Bbs, int ldb,
    float* __restrict__ Cqk, long long Cbs, int ldc,
    __half* __restrict__ Cu, long long Ubs,
    int K)
{
    __shared__ float As[STG][BKK][APAD];
    __shared__ float Bs[STG][BKK][BPAD];

    int n = blockIdx.z;
    B += (size_t)n * Bbs;

    int m_blk = blockIdx.x * BM, n_blk = blockIdx.y * BN;
    int tid = threadIdx.x, warp = tid >> 5, lane = tid & 31;
    int wm = (warp >> 2) * 32, wn = (warp & 3) * 32;
    int lr = lane >> 2, lc = lane & 3;

    float c[2][4][4];
#pragma unroll
    for (int i = 0; i < 2; ++i)
#pragma unroll
        for (int j = 0; j < 4; ++j)
#pragma unroll
            for (int q = 0; q < 4; ++q) c[i][j][q] = 0.f;

    int ar = tid >> 4, ac = (tid & 15) << 2;
    int KT = K / BKK;

    auto issue = [&](int kt, int buf) {
        cpa16(&As[buf][ar][ac], A + (size_t)(kt * BKK + ar) * lda + m_blk + ac);
#pragma unroll
        for (int i = 0; i < 2; ++i) {
            int idx = tid + (i << 8);
            int br = idx >> 5, bc = (idx & 31) << 2;
            cpa16(&Bs[buf][br][bc], B + (size_t)(kt * BKK + br) * ldb + n_blk + bc);
        }
    };

    for (int s = 0; s < STG - 1; ++s) {
        if (s < KT) issue(s, s);
        asm volatile("cp.async.commit_group;");
    }

    for (int kt = 0; kt < KT; ++kt) {
        asm volatile("cp.async.wait_group %0;" :: "n"(STG - 2));
        __syncthreads();
        int buf = kt % STG;

        unsigned a[2][4], b[4][2];
#pragma unroll
        for (int mt = 0; mt < 2; ++mt) {
            int mb = wm + mt * 16;
            a[mt][0] = packh2(As[buf][2*lc][mb+lr],     As[buf][2*lc+1][mb+lr]);
            a[mt][1] = packh2(As[buf][2*lc][mb+lr+8],   As[buf][2*lc+1][mb+lr+8]);
            a[mt][2] = packh2(As[buf][2*lc+8][mb+lr],   As[buf][2*lc+9][mb+lr]);
            a[mt][3] = packh2(As[buf][2*lc+8][mb+lr+8], As[buf][2*lc+9][mb+lr+8]);
        }
#pragma unroll
        for (int nt = 0; nt < 4; ++nt) {
            int nb = wn + nt * 8;
            b[nt][0] = packh2(Bs[buf][2*lc][nb+lr],   Bs[buf][2*lc+1][nb+lr]);
            b[nt][1] = packh2(Bs[buf][2*lc+8][nb+lr], Bs[buf][2*lc+9][nb+lr]);
        }
#pragma unroll
        for (int mt = 0; mt < 2; ++mt)
#pragma unroll
            for (int nt = 0; nt < 4; ++nt)
                mma16h(c[mt][nt], a[mt], b[nt]);

        __syncthreads();
        int nx = kt + STG - 1;
        if (nx < KT) issue(nx, nx % STG);
        asm volatile("cp.async.commit_group;");
    }

    if (blockIdx.x == 0) {
        float* C = Cqk + (size_t)n * Cbs;
#pragma unroll
        for (int mt = 0; mt < 2; ++mt)
#pragma unroll
            for (int nt = 0; nt < 4; ++nt) {
                int r0 = m_blk + wm + mt * 16 + lr;
                int c0 = n_blk + wn + nt * 8 + lc * 2;
                *(float2*)(C + (size_t)r0 * ldc + c0)       = make_float2(c[mt][nt][0], c[mt][nt][1]);
                *(float2*)(C + (size_t)(r0 + 8) * ldc + c0) = make_float2(c[mt][nt][2], c[mt][nt][3]);
            }
    } else {
        __half* U = Cu + (size_t)n * Ubs;
#pragma unroll
        for (int mt = 0; mt < 2; ++mt)
#pragma unroll
            for (int nt = 0; nt < 4; ++nt) {
                int r0 = m_blk - 64 + wm + mt * 16 + lr;
                int c0 = n_blk + wn + nt * 8 + lc * 2;
                *(__half2*)(U + (size_t)r0 * HW + c0) =
                    __floats2half2_rn(c[mt][nt][0] * USCALE, c[mt][nt][1] * USCALE);
                *(__half2*)(U + (size_t)(r0 + 8) * HW + c0) =
                    __floats2half2_rn(c[mt][nt][2] * USCALE, c[mt][nt][3] * USCALE);
            }
    }
}

// ---------------- qk2h: transpose Q/K fp32 [m][l] -> fp16 [l][32] rows ----------------
// grid (HW/32, 2, NB), block (32, 8). y=0 -> Qh (m 0..31), y=1 -> Kh (m 32..63)
__global__ void qk2h() {
    __shared__ float t[32][33];
    int n = blockIdx.z;
    int l0 = blockIdx.x * 32;
    int m0 = blockIdx.y * 32;
    int tx = threadIdx.x, ty = threadIdx.y;
    const float* src = g_QKU + (size_t)n * MALL * HW;
#pragma unroll
    for (int i = 0; i < 4; ++i) {
        int mm = ty + i * 8;
        t[mm][tx] = src[(size_t)(m0 + mm) * HW + l0 + tx];
    }
    __syncthreads();
    __half* dst = (blockIdx.y == 0 ? g_Qh : g_Kh) + (size_t)n * HW * 32;
#pragma unroll
    for (int i = 0; i < 4; ++i) {
        int ll = ty + i * 8;
        dst[(size_t)(l0 + ll) * 32 + tx] = __float2half_rn(t[tx][ll]);
    }
}

// ---------------- E' v3: 128x128 tiles, fp16 ldmatrix operands (SW64), shuffle z ----------------
// P^T[j][i] = exp(sum_k Kh[j][k] Qh[i][k]); A = Kh (m=j), B = Qh (n=i)
#define E_BM  128
#define E_BN  128
#define SWZ64(off) ((off) ^ (((off) >> 3) & 0x30))

__global__ void __launch_bounds__(256) gemm_e3(
    const __half* __restrict__ Ag, const __half* __restrict__ Bg,
    __half* __restrict__ C, long long Cbs, int ldc,
    float* __restrict__ gz)
{
    __shared__ __align__(1024) char asm_[8192];   // A tile 128 x 64B, SW64
    __shared__ __align__(1024) char bsm_[8192];   // B tile
    __shared__ float zpart[E_BN];

    int n = blockIdx.z;
    Ag += (size_t)n * HW * 32;
    Bg += (size_t)n * HW * 32;
    C  += (size_t)n * Cbs;

    int m_blk = blockIdx.y * E_BM, n_blk = blockIdx.x * E_BN;
    int tid = threadIdx.x, warp = tid >> 5, lane = tid & 31;
    int wm = (warp >> 1) * 32, wn = (warp & 1) * 64;
    int lr = lane >> 2, lc = lane & 3;
    int sub = lane >> 3, rs = lane & 7;

    if (tid < E_BN) zpart[tid] = 0.f;

    // single-shot load: 512 16B chunks per matrix, 2 per thread each
#pragma unroll
    for (int j = 0; j < 2; ++j) {
        int id = tid + (j << 8);          // 0..511
        int row = id >> 2, u = id & 3;
        uint32_t so = SWZ64((uint32_t)(row * 64 + u * 16));
        cpa16(asm_ + so, Ag + (size_t)(m_blk + row) * 32 + u * 8);
        cpa16(bsm_ + so, Bg + (size_t)(n_blk + row) * 32 + u * 8);
    }
    asm volatile("cp.async.commit_group;");
    asm volatile("cp.async.wait_group 0;");
    __syncthreads();

    uint32_t aT = smem_u32(asm_), bT = smem_u32(bsm_);
    int arow0 = wm + (sub & 1) * 8 + rs;
    int au    = sub >> 1;
    int brow0 = wn + (sub >> 1) * 8 + rs;
    int bu    = sub & 1;

    float c[2][8][4];
#pragma unroll
    for (int i = 0; i < 2; ++i)
#pragma unroll
        for (int j = 0; j < 8; ++j)
#pragma unroll
            for (int q = 0; q < 4; ++q) c[i][j][q] = 0.f;

#pragma unroll
    for (int ks = 0; ks < 2; ++ks) {
        unsigned a[2][4], b[8][2];
#pragma unroll
        for (int mt = 0; mt < 2; ++mt) {
            uint32_t addr = aT + SWZ64((uint32_t)((arow0 + mt * 16) * 64 + (ks * 2 + au) * 16));
            ldm_x4(a[mt][0], a[mt][1], a[mt][2], a[mt][3], addr);
        }
#pragma unroll
        for (int p = 0; p < 4; ++p) {
            uint32_t addr = bT + SWZ64((uint32_t)((brow0 + p * 16) * 64 + (ks * 2 + bu) * 16));
            ldm_x4(b[2 * p][0], b[2 * p][1], b[2 * p + 1][0], b[2 * p + 1][1], addr);
        }
#pragma unroll
        for (int mt = 0; mt < 2; ++mt)
#pragma unroll
            for (int nt = 0; nt < 8; ++nt)
                mma16h(c[mt][nt], a[mt], b[nt]);
    }

    // epilogue: exp, fp16 store, shuffle-reduced z column sums
#pragma unroll
    for (int mt = 0; mt < 2; ++mt)
#pragma unroll
        for (int nt = 0; nt < 8; ++nt) {
#pragma unroll
            for (int q = 0; q < 4; ++q) c[mt][nt][q] = __expf(c[mt][nt][q]);
            int r0 = m_blk + wm + mt * 16 + lr;
            int c0 = n_blk + wn + nt * 8 + lc * 2;
            *(__half2*)(C + (size_t)r0 * ldc + c0) =
                __floats2half2_rn(c[mt][nt][0], c[mt][nt][1]);
            *(__half2*)(C + (size_t)(r0 + 8) * ldc + c0) =
                __floats2half2_rn(c[mt][nt][2], c[mt][nt][3]);
        }
#pragma unroll
    for (int nt = 0; nt < 8; ++nt) {
#pragma unroll
        for (int cp = 0; cp < 2; ++cp) {
            float s = c[0][nt][cp] + c[0][nt][cp + 2] + c[1][nt][cp] + c[1][nt][cp + 2];
            s += __shfl_xor_sync(~0u, s, 4);
            s += __shfl_xor_sync(~0u, s, 8);
            s += __shfl_xor_sync(~0u, s, 16);
            if (lane < 4)
                atomicAdd(&zpart[wn + nt * 8 + 2 * lc + cp], s);
        }
    }
    __syncthreads();
    if (tid < E_BN) atomicAdd(&gz[(size_t)n * HW + n_blk + tid], zpart[tid]);
}

// ---------------- zscale v3: vectorized, Uh *= 1/z in place (8 halves / thread) ----------------
__global__ void zscale() {
    int n = blockIdx.y;
    int idx = blockIdx.x * blockDim.x + threadIdx.x;   // 8-half group index
    int base = idx * 8;
    int o = base >> 12;
    int i = base & (HW - 1);
    float4* up = (float4*)(g_Uh + ((size_t)n * CC + o) * HW + i);
    const float4* zp = (const float4*)(g_Z + (size_t)n * HW + i);
    float4 uraw = *up;
    float4 z0 = zp[0], z1 = zp[1];
    __half2* uh = (__half2*)&uraw;
    float2 v0 = __half22float2(uh[0]);
    float2 v1 = __half22float2(uh[1]);
    float2 v2 = __half22float2(uh[2]);
    float2 v3 = __half22float2(uh[3]);
    v0.x /= z0.x; v0.y /= z0.y; v1.x /= z0.z; v1.y /= z0.w;
    v2.x /= z1.x; v2.y /= z1.y; v3.x /= z1.z; v3.y /= z1.w;
    uh[0] = __floats2half2_rn(v0.x, v0.y);
    uh[1] = __floats2half2_rn(v1.x, v1.y);
    uh[2] = __floats2half2_rn(v2.x, v2.y);
    uh[3] = __floats2half2_rn(v3.x, v3.y);
    *up = uraw;
}

// ================= K5 v7: NT fp16 GEMM, 128x64 tiles, f32 accum =================
#define K5_BM   128
#define K5_BN   64
#define K5_BK   64
#define K5_STG  3
#define K5_A_BYTES 16384
#define K5_B_BYTES 8192
#define K5_STAGE   (K5_A_BYTES + K5_B_BYTES)
#define K5_SMEM    (K5_STG * K5_STAGE)       // 73728 bytes -> occ 3

#define SWZ(off) ((off) ^ (((off) >> 3) & 0x70))

__global__ void __launch_bounds__(256, 3) gemm_nt_f16_v7(
    const __half* __restrict__ A, const __half* __restrict__ B,
    float* __restrict__ C)
{
    extern __shared__ __align__(1024) char dsm[];
    uint32_t sbase = smem_u32(dsm);

    int n = blockIdx.z;
    const __half* Ab = A + (size_t)n * CC * HW + (size_t)(blockIdx.x * K5_BM) * HW;
    const __half* Bb = B + (size_t)n * HW * HW + (size_t)(blockIdx.y * K5_BN) * HW;
    float* Cb = C + (size_t)n * CC * HW + (size_t)(blockIdx.x * K5_BM) * HW + blockIdx.y * K5_BN;

    int tid = threadIdx.x, warp = tid >> 5, lane = tid & 31;
    int wm = (warp >> 1) * 32, wn = (warp & 1) * 32;
    int gr = lane >> 2, q4 = lane & 3;
    int sub = lane >> 3, rs = lane & 7;

    float c[2][4][4];
#pragma unroll
    for (int i = 0; i < 2; ++i)
#pragma unroll
        for (int j = 0; j < 4; ++j)
#pragma unroll
            for (int p = 0; p < 4; ++p) c[i][j][p] = 0.f;

    const int KT = HW / K5_BK;   // 64

    auto issue = [&](int kt, int s) {
        int k0 = kt * K5_BK;
        char* abase = dsm + (size_t)s * K5_STAGE;
        char* bbase = abase + K5_A_BYTES;
#pragma unroll
        for (int j = 0; j < 4; ++j) {
            int id = tid + (j << 8);
            int row = id >> 3, ch = id & 7;
            uint32_t so = SWZ((uint32_t)(row * 128 + ch * 16));
            cpa16(abase + so, Ab + (size_t)row * HW + k0 + ch * 8);
        }
#pragma unroll
        for (int j = 0; j < 2; ++j) {
            int id = tid + (j << 8);
            int row = id >> 3, ch = id & 7;
            uint32_t so = SWZ((uint32_t)(row * 128 + ch * 16));
            cpa16(bbase + so, Bb + (size_t)row * HW + k0 + ch * 8);
        }
    };

    issue(0, 0);
    asm volatile("cp.async.commit_group;");
    issue(1, 1);
    asm volatile("cp.async.commit_group;");

    int arow0 = wm + (sub & 1) * 8 + rs;
    int au    = sub >> 1;
    int brow0 = wn + (sub >> 1) * 8 + rs;
    int bu    = sub & 1;

    for (int kt = 0; kt < KT; ++kt) {
        asm volatile("cp.async.wait_group 1;");
        __syncthreads();
        int nx = kt + 2;
        if (nx < KT) issue(nx, nx % K5_STG);
        asm volatile("cp.async.commit_group;");

        int buf = kt % K5_STG;
        uint32_t aT = sbase + (uint32_t)buf * K5_STAGE;
        uint32_t bT = aT + K5_A_BYTES;

#pragma unroll
        for (int ks = 0; ks < 4; ++ks) {
            unsigned a[2][4], b[4][2];
#pragma unroll
            for (int mt = 0; mt < 2; ++mt) {
                uint32_t addr = aT + SWZ((uint32_t)((arow0 + mt * 16) * 128 + (ks * 2 + au) * 16));
                ldm_x4(a[mt][0], a[mt][1], a[mt][2], a[mt][3], addr);
            }
#pragma unroll
            for (int p = 0; p < 2; ++p) {
                uint32_t addr = bT + SWZ((uint32_t)((brow0 + p * 16) * 128 + (ks * 2 + bu) * 16));
                ldm_x4(b[2 * p][0], b[2 * p][1], b[2 * p + 1][0], b[2 * p + 1][1], addr);
            }
#pragma unroll
            for (int mt = 0; mt < 2; ++mt)
#pragma unroll
                for (int nt = 0; nt < 4; ++nt)
                    mma16h(c[mt][nt], a[mt], b[nt]);
        }
    }

#pragma unroll
    for (int mt = 0; mt < 2; ++mt) {
        int r0 = wm + mt * 16 + gr;
#pragma unroll
        for (int nt = 0; nt < 4; ++nt) {
            int c0 = wn + nt * 8 + 2 * q4;
            *(float2*)(Cb + (size_t)r0 * HW + c0) =
                make_float2(c[mt][nt][0] * UNSCALE, c[mt][nt][1] * UNSCALE);
            *(float2*)(Cb + (size_t)(r0 + 8) * HW + c0) =
                make_float2(c[mt][nt][2] * UNSCALE, c[mt][nt][3] * UNSCALE);
        }
    }
}

// ---------------- launch ----------------
extern "C" void kernel_launch(void* const* d_in, const int* in_sizes, int n_in,
                              void* d_out, int out_size) {
    const float* x  = (const float*)d_in[0];
    const float* Wq = (const float*)d_in[1];
    const float* Wk = (const float*)d_in[2];
    const float* Wv = (const float*)d_in[3];
    const float* Wo = (const float*)d_in[4];
    const float* gm = (const float*)d_in[5];
    float* out = (float*)d_out;

    float *wall, *qku, *gz;
    __half *uh, *ph, *qh, *kh;
    cudaGetSymbolAddress((void**)&wall, g_WallT);
    cudaGetSymbolAddress((void**)&qku,  g_QKU);
    cudaGetSymbolAddress((void**)&gz,   g_Z);
    cudaGetSymbolAddress((void**)&uh,   g_Uh);
    cudaGetSymbolAddress((void**)&ph,   g_Ph);
    cudaGetSymbolAddress((void**)&qh,   g_Qh);
    cudaGetSymbolAddress((void**)&kh,   g_Kh);

    // K0: combined weights + zero z
    build_wall<<<80, 256>>>(Wq, Wk, Wv, Wo, gm);

    // K1: Q/K rows -> fp32 g_QKU (block x=0); U rows -> fp16*2^12 g_Uh (blocks x>0)
    gemm_tn<<<dim3(MALL / BM, HW / BN, NB), 256>>>(
        wall, MALL,
        x, (long long)CC * HW, HW,
        qku, (long long)MALL * HW, HW,
        uh, (long long)CC * HW,
        CC);

    // transpose Q/K to fp16 [l][32] rows for ldmatrix
    qk2h<<<dim3(HW / 32, 2, NB), dim3(32, 8)>>>();

    // E' v3: fp16 ldmatrix operands, single-shot tiles, shuffle z-reduction
    gemm_e3<<<dim3(HW / E_BN, HW / E_BM, NB), 256>>>(
        kh, qh,
        ph, (long long)HW * HW, HW,
        gz);

    // zscale: Uh *= 1/z (vectorized, in place)
    zscale<<<dim3(CC * HW / 2048, NB), 256>>>();

    // K5 v7: fp16 NT GEMM (128x64 tiles, f32 accum)
    cudaFuncSetAttribute(gemm_nt_f16_v7, cudaFuncAttributeMaxDynamicSharedMemorySize, K5_SMEM);
    gemm_nt_f16_v7<<<dim3(CC / K5_BM, HW / K5_BN, NB), 256, K5_SMEM>>>(uh, ph, out);
}